// round 5
// baseline (speedup 1.0000x reference)
#include <cuda_runtime.h>
#include <cstdint>

#define M_DIM 4096
#define K_DIM 4096
#define N_DIM 11008
#define PK    2048

#define BM 128
#define BN 128
#define BK 32
#define THREADS 256

#define SA 36                 // As row stride in floats (conflict-free for A frags)
#define SB 136                // Bs row stride in floats (conflict-free for B frags)
#define A_TILE (BM * SA)      // 4608 floats
#define B_TILE (BK * SB)      // 4352 floats
#define SMEM_BYTES ((2 * A_TILE + 2 * B_TILE) * 4)   // 71680 B

__device__ float g_rowsum[M_DIM];

// ---------------------------------------------------------------------------
// rowsum_x[m] = sum_k x[m,k]   (hoisted zero-point term)
// ---------------------------------------------------------------------------
__global__ __launch_bounds__(256) void rowsum_kernel(const float* __restrict__ x) {
    __shared__ float red[8];
    const int m = blockIdx.x;
    const float4* row = reinterpret_cast<const float4*>(x + (size_t)m * K_DIM);
    float s = 0.f;
    for (int i = threadIdx.x; i < K_DIM / 4; i += 256) {
        float4 v = row[i];
        s += (v.x + v.y) + (v.z + v.w);
    }
    #pragma unroll
    for (int o = 16; o; o >>= 1) s += __shfl_xor_sync(0xffffffff, s, o);
    if ((threadIdx.x & 31) == 0) red[threadIdx.x >> 5] = s;
    __syncthreads();
    if (threadIdx.x < 8) {
        s = red[threadIdx.x];
        #pragma unroll
        for (int o = 4; o; o >>= 1) s += __shfl_xor_sync(0xff, s, o);
        if (threadIdx.x == 0) g_rowsum[m] = s;
    }
}

// ---------------------------------------------------------------------------
// helpers
// ---------------------------------------------------------------------------
__device__ __forceinline__ uint32_t f2tf32(float f) {
    uint32_t r;
    asm("cvt.rna.tf32.f32 %0, %1;" : "=r"(r) : "f"(f));
    return r;
}

__device__ __forceinline__ void mma_tf32(float c[4],
                                         uint32_t a0, uint32_t a1, uint32_t a2, uint32_t a3,
                                         uint32_t b0, uint32_t b1) {
    asm volatile(
        "mma.sync.aligned.m16n8k8.row.col.f32.tf32.tf32.f32 "
        "{%0,%1,%2,%3},{%4,%5,%6,%7},{%8,%9},{%0,%1,%2,%3};"
        : "+f"(c[0]), "+f"(c[1]), "+f"(c[2]), "+f"(c[3])
        : "r"(a0), "r"(a1), "r"(a2), "r"(a3), "r"(b0), "r"(b1));
}

__device__ __forceinline__ void cp_async16(float* dst_smem, const float* src_gmem) {
    uint32_t dst = (uint32_t)__cvta_generic_to_shared(dst_smem);
    asm volatile("cp.async.cg.shared.global [%0], [%1], 16;" :: "r"(dst), "l"(src_gmem));
}

// ---------------------------------------------------------------------------
// Main GEMM: out = scale * (x @ q - zero * rowsum_x)
// ---------------------------------------------------------------------------
extern __shared__ float smem[];

__global__ __launch_bounds__(THREADS, 2)
void asymm_quant_gemm_kernel(const float* __restrict__ x,
                             const int*   __restrict__ wp,
                             const float* __restrict__ wscale,
                             const float* __restrict__ wzero,
                             float*       __restrict__ out) {
    // ---- GROUP_M tile swizzle for L2 reuse ----
    const int num_pid_n = N_DIM / BN;   // 86
    const int num_pid_m = M_DIM / BM;   // 32
    const int GM = 8;
    int pid = blockIdx.x;
    int group_size = GM * num_pid_n;
    int group = pid / group_size;
    int first_m = group * GM;
    int gm = (num_pid_m - first_m < GM) ? (num_pid_m - first_m) : GM;
    int pid_m = first_m + (pid % gm);
    int pid_n = (pid % group_size) / gm;

    const int m0 = pid_m * BM;
    const int n0 = pid_n * BN;

    const int tid  = threadIdx.x;
    const int warp = tid >> 5;
    const int lane = tid & 31;
    const int g = lane >> 2;   // groupID (0..7)
    const int t = lane & 3;    // threadID in group (0..3)
    const int wm = warp >> 2;  // 0..1  (M dim of warp grid)
    const int wn = warp & 3;   // 0..3  (N dim of warp grid)

    float* As = smem;                 // 2 stages of [BM][SA]
    float* Bs = smem + 2 * A_TILE;    // 2 stages of [BK][SB]

    float acc[4][4][4];
    #pragma unroll
    for (int i = 0; i < 4; i++)
        #pragma unroll
        for (int j = 0; j < 4; j++)
            #pragma unroll
            for (int r = 0; r < 4; r++) acc[i][j][r] = 0.f;

    // ---- stage loaders ----
    // x tile: BM rows x BK floats, 8x 16B chunks per row, 1024 chunks / 256 thr
    auto loadX = [&](int kt, int stage) {
        const float* src0 = x + (size_t)m0 * K_DIM + kt * BK;
        float* dstb = As + stage * A_TILE;
        #pragma unroll
        for (int i = 0; i < 4; i++) {
            int c = tid + i * 256;
            int row = c >> 3, ch = c & 7;
            cp_async16(dstb + row * SA + ch * 4,
                       src0 + (size_t)row * K_DIM + ch * 4);
        }
    };

    // packed weight tile: 16 rows x 128 int32 = 512 int4-chunks / 256 thr
    auto loadW = [&](int kt, int4& p0, int4& p1) {
        const int pk0 = kt * (BK / 2);
        {
            int c = tid;       int row = c >> 5, col4 = c & 31;
            p0 = *reinterpret_cast<const int4*>(wp + (size_t)(pk0 + row) * N_DIM + n0 + col4 * 4);
        }
        {
            int c = tid + 256; int row = c >> 5, col4 = c & 31;
            p1 = *reinterpret_cast<const int4*>(wp + (size_t)(pk0 + row) * N_DIM + n0 + col4 * 4);
        }
    };

    auto storeW = [&](int stage, const int4& p, int c) {
        int row = c >> 5, col4 = c & 31;
        float* base = Bs + stage * B_TILE;
        float4 lo, hi;
        lo.x = (float)(p.x & 15);        lo.y = (float)(p.y & 15);
        lo.z = (float)(p.z & 15);        lo.w = (float)(p.w & 15);
        hi.x = (float)((p.x >> 4) & 15); hi.y = (float)((p.y >> 4) & 15);
        hi.z = (float)((p.z >> 4) & 15); hi.w = (float)((p.w >> 4) & 15);
        *reinterpret_cast<float4*>(base + (2 * row    ) * SB + col4 * 4) = lo;
        *reinterpret_cast<float4*>(base + (2 * row + 1) * SB + col4 * 4) = hi;
    };

    auto compute = [&](int stage) {
        const float* As_ = As + stage * A_TILE + (wm * 64 + g) * SA;
        const float* Bs_ = Bs + stage * B_TILE + (wn * 32 + g);
        #pragma unroll
        for (int kk = 0; kk < 4; kk++) {
            uint32_t a[4][4];
            #pragma unroll
            for (int mt = 0; mt < 4; mt++) {
                const float* p = As_ + mt * 16 * SA + kk * 8 + t;
                a[mt][0] = f2tf32(p[0]);
                a[mt][1] = f2tf32(p[8 * SA]);
                a[mt][2] = f2tf32(p[4]);
                a[mt][3] = f2tf32(p[8 * SA + 4]);
            }
            uint32_t b[4][2];
            #pragma unroll
            for (int nt = 0; nt < 4; nt++) {
                const float* p = Bs_ + (kk * 8 + t) * SB + nt * 8;
                b[nt][0] = __float_as_uint(p[0]);    // exact small ints: valid tf32 as-is
                b[nt][1] = __float_as_uint(p[4 * SB]);
            }
            #pragma unroll
            for (int mt = 0; mt < 4; mt++)
                #pragma unroll
                for (int nt = 0; nt < 4; nt++)
                    mma_tf32(acc[mt][nt], a[mt][0], a[mt][1], a[mt][2], a[mt][3],
                             b[nt][0], b[nt][1]);
        }
    };

    // ---- prologue: stage 0 ----
    int4 p0, p1;
    loadX(0, 0);
    asm volatile("cp.async.commit_group;");
    loadW(0, p0, p1);
    asm volatile("cp.async.wait_group 0;");
    storeW(0, p0, tid);
    storeW(0, p1, tid + 256);
    __syncthreads();

    // ---- main loop ----
    const int NT = K_DIM / BK;   // 128
    for (int kt = 0; kt < NT; kt++) {
        int cur = kt & 1, nxt = cur ^ 1;
        bool has_next = (kt + 1 < NT);
        if (has_next) {
            loadX(kt + 1, nxt);
            asm volatile("cp.async.commit_group;");
            loadW(kt + 1, p0, p1);
        }
        compute(cur);
        if (has_next) {
            asm volatile("cp.async.wait_group 0;");
            storeW(nxt, p0, tid);
            storeW(nxt, p1, tid + 256);
        }
        __syncthreads();
    }

    // ---- epilogue: out = scale*(acc - zero*rowsum) ----
    #pragma unroll
    for (int mt = 0; mt < 4; mt++) {
        int r0 = m0 + wm * 64 + mt * 16 + g;
        float rs0 = g_rowsum[r0];
        float rs1 = g_rowsum[r0 + 8];
        #pragma unroll
        for (int nt = 0; nt < 4; nt++) {
            int col = n0 + wn * 32 + nt * 8 + t * 2;
            float2 sc = *reinterpret_cast<const float2*>(wscale + col);
            float2 zp = *reinterpret_cast<const float2*>(wzero + col);
            float2 o0, o1;
            o0.x = sc.x * (acc[mt][nt][0] - zp.x * rs0);
            o0.y = sc.y * (acc[mt][nt][1] - zp.y * rs0);
            o1.x = sc.x * (acc[mt][nt][2] - zp.x * rs1);
            o1.y = sc.y * (acc[mt][nt][3] - zp.y * rs1);
            *reinterpret_cast<float2*>(out + (size_t)r0 * N_DIM + col) = o0;
            *reinterpret_cast<float2*>(out + (size_t)(r0 + 8) * N_DIM + col) = o1;
        }
    }
}

// ---------------------------------------------------------------------------
// launch
// ---------------------------------------------------------------------------
extern "C" void kernel_launch(void* const* d_in, const int* in_sizes, int n_in,
                              void* d_out, int out_size) {
    const float* x  = (const float*)d_in[0];
    const int*   wp = (const int*)d_in[1];
    const float* ws = (const float*)d_in[2];
    const float* wz = (const float*)d_in[3];
    float* out = (float*)d_out;

    cudaFuncSetAttribute(asymm_quant_gemm_kernel,
                         cudaFuncAttributeMaxDynamicSharedMemorySize, SMEM_BYTES);

    rowsum_kernel<<<M_DIM, 256>>>(x);

    const int grid = (M_DIM / BM) * (N_DIM / BN);   // 32 * 86 = 2752
    asymm_quant_gemm_kernel<<<grid, THREADS, SMEM_BYTES>>>(x, wp, ws, wz, out);
}

// round 6
// speedup vs baseline: 2.2087x; 2.2087x over previous
#include <cuda_runtime.h>
#include <cuda_fp16.h>
#include <cstdint>

#define M_DIM 4096
#define K_DIM 4096
#define N_DIM 11008

#define BM 128
#define BN 128
#define BK 64
#define NT (K_DIM / BK)        // 64 K-tiles
#define THREADS 256

#define A_STAGE 16384          // 128 rows x 128B (fp16, SW128)
#define B_STAGE 16384
#define STAGE_BYTES (A_STAGE + B_STAGE)
#define SMEM_BYTES (2 * STAGE_BYTES + 1024)

__device__ float g_rowsum[M_DIM];
__device__ __align__(16) __half g_xh[(size_t)M_DIM * K_DIM];   // x rounded to fp16

// ---------------------------------------------------------------------------
// pre-pass: x -> fp16 (round-to-nearest), rowsum of the ROUNDED values
// (keeps the zero-point hoist exact w.r.t. what the MMA actually consumes)
// ---------------------------------------------------------------------------
__global__ __launch_bounds__(256) void convert_rowsum_kernel(const float* __restrict__ x) {
    __shared__ float red[8];
    const int m = blockIdx.x;
    const float4* src = reinterpret_cast<const float4*>(x + (size_t)m * K_DIM);
    uint2* dst = reinterpret_cast<uint2*>(g_xh + (size_t)m * K_DIM);
    float s = 0.f;
    for (int i = threadIdx.x; i < K_DIM / 4; i += 256) {
        float4 v = src[i];
        __half2 h0 = __floats2half2_rn(v.x, v.y);
        __half2 h1 = __floats2half2_rn(v.z, v.w);
        uint2 u;
        u.x = *reinterpret_cast<uint32_t*>(&h0);
        u.y = *reinterpret_cast<uint32_t*>(&h1);
        dst[i] = u;
        float2 f0 = __half22float2(h0), f1 = __half22float2(h1);
        s += (f0.x + f0.y) + (f1.x + f1.y);
    }
    #pragma unroll
    for (int o = 16; o; o >>= 1) s += __shfl_xor_sync(0xffffffff, s, o);
    if ((threadIdx.x & 31) == 0) red[threadIdx.x >> 5] = s;
    __syncthreads();
    if (threadIdx.x < 8) {
        s = red[threadIdx.x];
        #pragma unroll
        for (int o = 4; o; o >>= 1) s += __shfl_xor_sync(0xff, s, o);
        if (threadIdx.x == 0) g_rowsum[m] = s;
    }
}

// ---------------------------------------------------------------------------
// helpers
// ---------------------------------------------------------------------------
__device__ __forceinline__ uint32_t smem_u32(const void* p) {
    uint32_t a;
    asm("{ .reg .u64 t; cvta.to.shared.u64 t, %1; cvt.u32.u64 %0, t; }" : "=r"(a) : "l"(p));
    return a;
}
__device__ __forceinline__ uint32_t swz(uint32_t off) {    // SW128: 8 rows x 128B atom
    return off ^ ((off >> 3) & 0x70);
}
__device__ __forceinline__ void cp_async16(uint32_t dst, const void* src) {
    asm volatile("cp.async.cg.shared.global [%0], [%1], 16;" :: "r"(dst), "l"(src));
}
__device__ __forceinline__ void ldmatrix_x4(uint32_t& r0, uint32_t& r1, uint32_t& r2,
                                            uint32_t& r3, uint32_t addr) {
    asm volatile("ldmatrix.sync.aligned.m8n8.x4.shared.b16 {%0,%1,%2,%3}, [%4];"
                 : "=r"(r0), "=r"(r1), "=r"(r2), "=r"(r3) : "r"(addr));
}
__device__ __forceinline__ void ldmatrix_x2(uint32_t& r0, uint32_t& r1, uint32_t addr) {
    asm volatile("ldmatrix.sync.aligned.m8n8.x2.shared.b16 {%0,%1}, [%2];"
                 : "=r"(r0), "=r"(r1) : "r"(addr));
}
__device__ __forceinline__ void mma_f16(float c[4], uint32_t a0, uint32_t a1,
                                        uint32_t a2, uint32_t a3,
                                        uint32_t b0, uint32_t b1) {
    asm volatile(
        "mma.sync.aligned.m16n8k16.row.col.f32.f16.f16.f32 "
        "{%0,%1,%2,%3},{%4,%5,%6,%7},{%8,%9},{%0,%1,%2,%3};"
        : "+f"(c[0]), "+f"(c[1]), "+f"(c[2]), "+f"(c[3])
        : "r"(a0), "r"(a1), "r"(a2), "r"(a3), "r"(b0), "r"(b1));
}
// nibble pair -> half2 {lo, hi} (values 0..15), via 1024-bias magic + hsub2
__device__ __forceinline__ uint32_t dequant_h2(int p) {
    uint32_t u = 0x64006400u | ((uint32_t)p & 0xFu) | (((uint32_t)p << 12) & 0xF0000u);
    __half2 h = *reinterpret_cast<__half2*>(&u);
    __half2 r = __hsub2(h, __floats2half2_rn(1024.f, 1024.f));
    return *reinterpret_cast<uint32_t*>(&r);
}

// ---------------------------------------------------------------------------
// Main GEMM: out = scale * (x_h @ q - zero * rowsum(x_h))
// ---------------------------------------------------------------------------
__global__ __launch_bounds__(THREADS, 2)
void asymm_quant_gemm_kernel(const int*   __restrict__ wp,
                             const float* __restrict__ wscale,
                             const float* __restrict__ wzero,
                             float*       __restrict__ out) {
    extern __shared__ char smem_raw[];
    const uint32_t tile0 = (smem_u32(smem_raw) + 1023u) & ~1023u;

    // ---- GROUP_M tile swizzle for L2 reuse ----
    const int num_pid_n = N_DIM / BN;   // 86
    const int num_pid_m = M_DIM / BM;   // 32
    const int GM = 8;
    int pid = blockIdx.x;
    int group_size = GM * num_pid_n;
    int group = pid / group_size;
    int first_m = group * GM;
    int gm = (num_pid_m - first_m < GM) ? (num_pid_m - first_m) : GM;
    int pid_m = first_m + (pid % gm);
    int pid_n = (pid % group_size) / gm;

    const int m0 = pid_m * BM;
    const int n0 = pid_n * BN;

    const int tid  = threadIdx.x;
    const int warp = tid >> 5;
    const int lane = tid & 31;
    const int g = lane >> 2;
    const int t = lane & 3;
    const int wm = warp >> 2;  // 0..1
    const int wn = warp & 3;   // 0..3

    // per-thread ldmatrix base addresses (stage 0, mt/nt 0, kstep 0)
    // A: rows = wm*64 + (lane&15), chunk = (lane>>4)&1
    const uint32_t a_base = tile0 +
        swz((uint32_t)((wm * 64 + (lane & 15)) * 128 + ((lane >> 4) & 1) * 16));
    // B: rows = wn*32 + (lane&7), chunk = (lane>>3)&1   (lanes 16-31 mirror 0-15)
    const uint32_t b_base = tile0 + A_STAGE +
        swz((uint32_t)((wn * 32 + (lane & 7)) * 128 + ((lane >> 3) & 1) * 16));

    float acc[4][4][4];
    #pragma unroll
    for (int i = 0; i < 4; i++)
        #pragma unroll
        for (int j = 0; j < 4; j++)
            #pragma unroll
            for (int r = 0; r < 4; r++) acc[i][j][r] = 0.f;

    // ---- A fill: 128 rows x 128B, 1024 chunks of 16B, 4 per thread ----
    auto fillA = [&](int kt, int stage) {
        const __half* src0 = g_xh + (size_t)m0 * K_DIM + kt * BK;
        const uint32_t dst0 = tile0 + stage * STAGE_BYTES;
        #pragma unroll
        for (int i = 0; i < 4; i++) {
            int c = tid + i * 256;
            int m = c >> 3, ch = c & 7;
            cp_async16(dst0 + swz((uint32_t)(m * 128 + ch * 16)),
                       src0 + (size_t)m * K_DIM + ch * 8);
        }
    };

    // ---- W load: 32 packed rows x 128 cols; thread -> col n=tid&127, half h=tid>>7
    const int wn_col = tid & 127;
    const int wh     = tid >> 7;
    auto loadW = [&](int kt, int* v) {
        const int* base = wp + (size_t)(kt * (BK / 2) + wh * 16) * N_DIM + n0 + wn_col;
        #pragma unroll
        for (int i = 0; i < 16; i++) v[i] = base[(size_t)i * N_DIM];
    };

    // ---- B store: row n, 32 halves (k = wh*32..+31) = chunks wh*4..wh*4+3 ----
    auto storeB = [&](int stage, const int* v) {
        const uint32_t bs0 = tile0 + stage * STAGE_BYTES + A_STAGE;
        #pragma unroll
        for (int j = 0; j < 4; j++) {
            uint32_t h0 = dequant_h2(v[4 * j + 0]);
            uint32_t h1 = dequant_h2(v[4 * j + 1]);
            uint32_t h2 = dequant_h2(v[4 * j + 2]);
            uint32_t h3 = dequant_h2(v[4 * j + 3]);
            uint32_t dst = bs0 + swz((uint32_t)(wn_col * 128 + (wh * 4 + j) * 16));
            asm volatile("st.shared.v4.b32 [%0], {%1,%2,%3,%4};"
                         :: "r"(dst), "r"(h0), "r"(h1), "r"(h2), "r"(h3) : "memory");
        }
    };

    // ---- compute one K-tile (4 k16 steps) ----
    auto compute = [&](int stage) {
        const uint32_t so = (uint32_t)(stage * STAGE_BYTES);
        #pragma unroll
        for (int ks = 0; ks < 4; ks++) {
            uint32_t a[4][4];
            #pragma unroll
            for (int mt = 0; mt < 4; mt++)
                ldmatrix_x4(a[mt][0], a[mt][1], a[mt][2], a[mt][3],
                            (a_base + so + mt * 2048) ^ (uint32_t)(ks * 32));
            uint32_t b[4][2];
            #pragma unroll
            for (int nt = 0; nt < 4; nt++)
                ldmatrix_x2(b[nt][0], b[nt][1],
                            (b_base + so + nt * 1024) ^ (uint32_t)(ks * 32));
            #pragma unroll
            for (int mt = 0; mt < 4; mt++)
                #pragma unroll
                for (int nt = 0; nt < 4; nt++)
                    mma_f16(acc[mt][nt], a[mt][0], a[mt][1], a[mt][2], a[mt][3],
                            b[nt][0], b[nt][1]);
        }
    };

    // ---- prologue: stage 0 ----
    int v[16];
    fillA(0, 0);
    asm volatile("cp.async.commit_group;");
    loadW(0, v);
    asm volatile("cp.async.wait_group 0;");
    storeB(0, v);
    __syncthreads();

    // ---- main loop ----
    for (int kt = 0; kt < NT; kt++) {
        int cur = kt & 1, nxt = cur ^ 1;
        bool has_next = (kt + 1 < NT);
        if (has_next) {
            fillA(kt + 1, nxt);
            asm volatile("cp.async.commit_group;");
            loadW(kt + 1, v);
        }
        compute(cur);
        if (has_next) {
            asm volatile("cp.async.wait_group 0;");
            storeB(nxt, v);
        }
        __syncthreads();
    }

    // ---- epilogue: out = scale*(acc - zero*rowsum) ----
    #pragma unroll
    for (int mt = 0; mt < 4; mt++) {
        int r0 = m0 + wm * 64 + mt * 16 + g;
        float rs0 = g_rowsum[r0];
        float rs1 = g_rowsum[r0 + 8];
        #pragma unroll
        for (int nt = 0; nt < 4; nt++) {
            int col = n0 + wn * 32 + nt * 8 + t * 2;
            float2 sc = *reinterpret_cast<const float2*>(wscale + col);
            float2 zp = *reinterpret_cast<const float2*>(wzero + col);
            float2 o0, o1;
            o0.x = sc.x * (acc[mt][nt][0] - zp.x * rs0);
            o0.y = sc.y * (acc[mt][nt][1] - zp.y * rs0);
            o1.x = sc.x * (acc[mt][nt][2] - zp.x * rs1);
            o1.y = sc.y * (acc[mt][nt][3] - zp.y * rs1);
            *reinterpret_cast<float2*>(out + (size_t)r0 * N_DIM + col) = o0;
            *reinterpret_cast<float2*>(out + (size_t)(r0 + 8) * N_DIM + col) = o1;
        }
    }
}

// ---------------------------------------------------------------------------
// launch
// ---------------------------------------------------------------------------
extern "C" void kernel_launch(void* const* d_in, const int* in_sizes, int n_in,
                              void* d_out, int out_size) {
    const float* x  = (const float*)d_in[0];
    const int*   wp = (const int*)d_in[1];
    const float* ws = (const float*)d_in[2];
    const float* wz = (const float*)d_in[3];
    float* out = (float*)d_out;

    cudaFuncSetAttribute(asymm_quant_gemm_kernel,
                         cudaFuncAttributeMaxDynamicSharedMemorySize, SMEM_BYTES);

    convert_rowsum_kernel<<<M_DIM, 256>>>(x);

    const int grid = (M_DIM / BM) * (N_DIM / BN);   // 2752
    asymm_quant_gemm_kernel<<<grid, THREADS, SMEM_BYTES>>>(wp, ws, wz, out);
}

// round 7
// speedup vs baseline: 2.5101x; 1.1365x over previous
#include <cuda_runtime.h>
#include <cuda_fp16.h>
#include <cstdint>

#define M_DIM 4096
#define K_DIM 4096
#define N_DIM 11008
#define PK    2048

#define BM 128
#define BN 128
#define BK 64
#define NT (K_DIM / BK)        // 64 K-tiles
#define THREADS 256
#define STAGES 3

#define A_STAGE 16384          // 128 rows x 128B (fp16, SW128)
#define B_STAGE 16384
#define STAGE_BYTES (A_STAGE + B_STAGE)
#define SMEM_BYTES (STAGES * STAGE_BYTES + 1024)   // ~97.3 KB, 2 CTAs/SM

__device__ float g_rowsum[M_DIM];
__device__ __align__(16) __half g_xh[(size_t)M_DIM * K_DIM];   // x rounded to fp16
__device__ __align__(16) __half g_bh[(size_t)N_DIM * K_DIM];   // dequant q, [N][K] k-major

// ---------------------------------------------------------------------------
// helpers
// ---------------------------------------------------------------------------
__device__ __forceinline__ uint32_t smem_u32(const void* p) {
    uint32_t a;
    asm("{ .reg .u64 t; cvta.to.shared.u64 t, %1; cvt.u32.u64 %0, t; }" : "=r"(a) : "l"(p));
    return a;
}
__device__ __forceinline__ uint32_t swz(uint32_t off) {    // SW128 swizzle
    return off ^ ((off >> 3) & 0x70);
}
__device__ __forceinline__ void cp_async16(uint32_t dst, const void* src) {
    asm volatile("cp.async.cg.shared.global [%0], [%1], 16;" :: "r"(dst), "l"(src));
}
__device__ __forceinline__ void ldmatrix_x4(uint32_t& r0, uint32_t& r1, uint32_t& r2,
                                            uint32_t& r3, uint32_t addr) {
    asm volatile("ldmatrix.sync.aligned.m8n8.x4.shared.b16 {%0,%1,%2,%3}, [%4];"
                 : "=r"(r0), "=r"(r1), "=r"(r2), "=r"(r3) : "r"(addr));
}
__device__ __forceinline__ void ldmatrix_x2(uint32_t& r0, uint32_t& r1, uint32_t addr) {
    asm volatile("ldmatrix.sync.aligned.m8n8.x2.shared.b16 {%0,%1}, [%2];"
                 : "=r"(r0), "=r"(r1) : "r"(addr));
}
__device__ __forceinline__ void mma_f16(float c[4], uint32_t a0, uint32_t a1,
                                        uint32_t a2, uint32_t a3,
                                        uint32_t b0, uint32_t b1) {
    asm volatile(
        "mma.sync.aligned.m16n8k16.row.col.f32.f16.f16.f32 "
        "{%0,%1,%2,%3},{%4,%5,%6,%7},{%8,%9},{%0,%1,%2,%3};"
        : "+f"(c[0]), "+f"(c[1]), "+f"(c[2]), "+f"(c[3])
        : "r"(a0), "r"(a1), "r"(a2), "r"(a3), "r"(b0), "r"(b1));
}
// nibble pair -> half2 {lo, hi} (exact values 0..15)
__device__ __forceinline__ uint32_t dequant_h2(int p) {
    uint32_t u = 0x64006400u | ((uint32_t)p & 0xFu) | (((uint32_t)p << 12) & 0xF0000u);
    __half2 h = *reinterpret_cast<__half2*>(&u);
    __half2 r = __hsub2(h, __floats2half2_rn(1024.f, 1024.f));
    return *reinterpret_cast<uint32_t*>(&r);
}

// ---------------------------------------------------------------------------
// pre-pass 1: x -> fp16 (rn) + rowsum of the ROUNDED values
// ---------------------------------------------------------------------------
__global__ __launch_bounds__(256) void convert_rowsum_kernel(const float* __restrict__ x) {
    __shared__ float red[8];
    const int m = blockIdx.x;
    const float4* src = reinterpret_cast<const float4*>(x + (size_t)m * K_DIM);
    uint2* dst = reinterpret_cast<uint2*>(g_xh + (size_t)m * K_DIM);
    float s = 0.f;
    for (int i = threadIdx.x; i < K_DIM / 4; i += 256) {
        float4 v = src[i];
        __half2 h0 = __floats2half2_rn(v.x, v.y);
        __half2 h1 = __floats2half2_rn(v.z, v.w);
        uint2 u;
        u.x = *reinterpret_cast<uint32_t*>(&h0);
        u.y = *reinterpret_cast<uint32_t*>(&h1);
        dst[i] = u;
        float2 f0 = __half22float2(h0), f1 = __half22float2(h1);
        s += (f0.x + f0.y) + (f1.x + f1.y);
    }
    #pragma unroll
    for (int o = 16; o; o >>= 1) s += __shfl_xor_sync(0xffffffff, s, o);
    if ((threadIdx.x & 31) == 0) red[threadIdx.x >> 5] = s;
    __syncthreads();
    if (threadIdx.x < 8) {
        s = red[threadIdx.x];
        #pragma unroll
        for (int o = 4; o; o >>= 1) s += __shfl_xor_sync(0xff, s, o);
        if (threadIdx.x == 0) g_rowsum[m] = s;
    }
}

// ---------------------------------------------------------------------------
// pre-pass 2: wp [PK][N] int32 (1 byte payload) -> g_bh [N][K] fp16 exact q
// block = (nb, kc); thread owns column n = nb*256+tid, 16B chunk kc (8 k-vals)
// ---------------------------------------------------------------------------
__global__ __launch_bounds__(256) void dequant_w_kernel(const int* __restrict__ wp) {
    const int bid = blockIdx.x;
    const int nb = bid / (K_DIM / 8);      // 0..42
    const int kc = bid % (K_DIM / 8);      // 0..511
    const int n  = nb * 256 + threadIdx.x; // 43*256 = 11008 exact
    const int p0 = kc * 4;
    uint32_t h[4];
    #pragma unroll
    for (int i = 0; i < 4; i++) {
        int v = wp[(size_t)(p0 + i) * N_DIM + n];   // coalesced across warp
        h[i] = dequant_h2(v);
    }
    *reinterpret_cast<uint4*>(g_bh + (size_t)n * K_DIM + kc * 8) =
        make_uint4(h[0], h[1], h[2], h[3]);
}

// ---------------------------------------------------------------------------
// Main GEMM: out = scale * (x_h @ q - zero * rowsum(x_h))
// Pure multistage: cp.async A+B, ldmatrix, HMMA. No LDG/ALU/STS in loop.
// ---------------------------------------------------------------------------
__global__ __launch_bounds__(THREADS, 2)
void asymm_quant_gemm_kernel(const float* __restrict__ wscale,
                             const float* __restrict__ wzero,
                             float*       __restrict__ out) {
    extern __shared__ char smem_raw[];
    const uint32_t tile0 = (smem_u32(smem_raw) + 1023u) & ~1023u;

    // ---- GROUP_M tile swizzle for L2 reuse ----
    const int num_pid_n = N_DIM / BN;   // 86
    const int num_pid_m = M_DIM / BM;   // 32
    const int GM = 8;
    int pid = blockIdx.x;
    int group_size = GM * num_pid_n;
    int group = pid / group_size;
    int first_m = group * GM;
    int gm = (num_pid_m - first_m < GM) ? (num_pid_m - first_m) : GM;
    int pid_m = first_m + (pid % gm);
    int pid_n = (pid % group_size) / gm;

    const int m0 = pid_m * BM;
    const int n0 = pid_n * BN;

    const int tid  = threadIdx.x;
    const int warp = tid >> 5;
    const int lane = tid & 31;
    const int g = lane >> 2;
    const int t = lane & 3;
    const int wm = warp >> 2;  // 0..1
    const int wn = warp & 3;   // 0..3

    // ldmatrix base addresses (slot 0, sub-tile 0, kstep 0)
    const uint32_t a_base = tile0 +
        swz((uint32_t)((wm * 64 + (lane & 15)) * 128 + ((lane >> 4) & 1) * 16));
    const uint32_t b_base = tile0 + A_STAGE +
        swz((uint32_t)((wn * 32 + (lane & 7)) * 128 + ((lane >> 3) & 1) * 16));

    float acc[4][4][4];
    #pragma unroll
    for (int i = 0; i < 4; i++)
        #pragma unroll
        for (int j = 0; j < 4; j++)
            #pragma unroll
            for (int r = 0; r < 4; r++) acc[i][j][r] = 0.f;

    // per-thread fill coords: 1024 16B-chunks per operand, 4 per thread
    auto fillStage = [&](int kt, int slot) {
        const uint32_t s0 = tile0 + slot * STAGE_BYTES;
        const __half* sa = g_xh + (size_t)m0 * K_DIM + kt * BK;
        const __half* sb = g_bh + (size_t)n0 * K_DIM + kt * BK;
        #pragma unroll
        for (int i = 0; i < 4; i++) {
            int c = tid + i * 256;
            int r = c >> 3, ch = c & 7;
            uint32_t off = swz((uint32_t)(r * 128 + ch * 16));
            cp_async16(s0 + off, sa + (size_t)r * K_DIM + ch * 8);
            cp_async16(s0 + A_STAGE + off, sb + (size_t)r * K_DIM + ch * 8);
        }
    };

    auto compute = [&](int slot) {
        const uint32_t so = (uint32_t)(slot * STAGE_BYTES);
        #pragma unroll
        for (int ks = 0; ks < 4; ks++) {
            uint32_t a[4][4];
            #pragma unroll
            for (int mt = 0; mt < 4; mt++)
                ldmatrix_x4(a[mt][0], a[mt][1], a[mt][2], a[mt][3],
                            (a_base + so + mt * 2048) ^ (uint32_t)(ks * 32));
            uint32_t b[4][2];
            #pragma unroll
            for (int nt = 0; nt < 4; nt++)
                ldmatrix_x2(b[nt][0], b[nt][1],
                            (b_base + so + nt * 1024) ^ (uint32_t)(ks * 32));
            #pragma unroll
            for (int mt = 0; mt < 4; mt++)
                #pragma unroll
                for (int nt = 0; nt < 4; nt++)
                    mma_f16(acc[mt][nt], a[mt][0], a[mt][1], a[mt][2], a[mt][3],
                            b[nt][0], b[nt][1]);
        }
    };

    // ---- prologue: stages 0,1 in flight ----
    fillStage(0, 0);
    asm volatile("cp.async.commit_group;");
    fillStage(1, 1);
    asm volatile("cp.async.commit_group;");
    asm volatile("cp.async.wait_group 1;");   // tile 0 ready
    __syncthreads();

    // ---- main loop: one barrier per K-tile ----
    for (int kt = 0; kt < NT; kt++) {
        compute(kt % STAGES);
        // fill tile kt+2 into slot (kt+2)%3 == (kt-1)%3 (readers done last iter)
        if (kt + 2 < NT) fillStage(kt + 2, (kt + 2) % STAGES);
        asm volatile("cp.async.commit_group;");
        asm volatile("cp.async.wait_group 1;");   // tile kt+1 ready
        __syncthreads();
    }

    // ---- epilogue: out = scale*(acc - zero*rowsum) ----
    #pragma unroll
    for (int mt = 0; mt < 4; mt++) {
        int r0 = m0 + wm * 64 + mt * 16 + g;
        float rs0 = g_rowsum[r0];
        float rs1 = g_rowsum[r0 + 8];
        #pragma unroll
        for (int nt = 0; nt < 4; nt++) {
            int col = n0 + wn * 32 + nt * 8 + t * 2;
            float2 sc = *reinterpret_cast<const float2*>(wscale + col);
            float2 zp = *reinterpret_cast<const float2*>(wzero + col);
            float2 o0, o1;
            o0.x = sc.x * (acc[mt][nt][0] - zp.x * rs0);
            o0.y = sc.y * (acc[mt][nt][1] - zp.y * rs0);
            o1.x = sc.x * (acc[mt][nt][2] - zp.x * rs1);
            o1.y = sc.y * (acc[mt][nt][3] - zp.y * rs1);
            *reinterpret_cast<float2*>(out + (size_t)r0 * N_DIM + col) = o0;
            *reinterpret_cast<float2*>(out + (size_t)(r0 + 8) * N_DIM + col) = o1;
        }
    }
}

// ---------------------------------------------------------------------------
// launch
// ---------------------------------------------------------------------------
extern "C" void kernel_launch(void* const* d_in, const int* in_sizes, int n_in,
                              void* d_out, int out_size) {
    const float* x  = (const float*)d_in[0];
    const int*   wp = (const int*)d_in[1];
    const float* ws = (const float*)d_in[2];
    const float* wz = (const float*)d_in[3];
    float* out = (float*)d_out;

    cudaFuncSetAttribute(asymm_quant_gemm_kernel,
                         cudaFuncAttributeMaxDynamicSharedMemorySize, SMEM_BYTES);

    convert_rowsum_kernel<<<M_DIM, 256>>>(x);
    dequant_w_kernel<<<(N_DIM / 256) * (K_DIM / 8), 256>>>(wp);

    const int grid = (M_DIM / BM) * (N_DIM / BN);   // 2752
    asymm_quant_gemm_kernel<<<grid, THREADS, SMEM_BYTES>>>(ws, wz, out);
}